// round 11
// baseline (speedup 1.0000x reference)
#include <cuda_runtime.h>
#include <math.h>

#define NB 128
#define NT 30
#define NG 13
#define NC 16
#define NROWS 507            // 169*3 anchor rows used per batch
#define ROWLEN 21
#define ROWS_FULL 10647
#define PSTRIDE 22           // padded row stride in smem

// packed scratch: bits[56:64) = arrival count, bits[0:56) = fixed-point sum (x 2^24)
__device__ unsigned long long g_pack = 0ULL;

__device__ __forceinline__ float warp_sum(float v) {
    #pragma unroll
    for (int o = 16; o > 0; o >>= 1) v += __shfl_down_sync(0xffffffffu, v, o);
    return v;
}

__global__ void __launch_bounds__(512) region_loss_kernel(
    const float* __restrict__ outp,   // (128, 10647, 21)
    const float* __restrict__ tgt,    // (128, 30, 5)
    float* __restrict__ loss)
{
    const int b   = blockIdx.x;
    const int tid = threadIdx.x;
    const size_t base = (size_t)b * ((size_t)ROWS_FULL * ROWLEN);

    __shared__ float s_ti[NT][5];        // x1,y1,x2,y2,cls
    __shared__ int   s_idx[NT];
    __shared__ float s_p[90 * PSTRIDE];  // staged target-cell rows
    __shared__ float s_warp[16];

    // ---- phase 0: conf loads + target table (issued together) ----
    float conf = 0.0f;
    if (tid < NROWS) conf = __ldg(outp + base + (size_t)tid * ROWLEN + 4);

    if (tid < NT) {
        const float* tg = tgt + ((size_t)b * NT + tid) * 5;
        const float x1 = __ldg(tg + 0), y1 = __ldg(tg + 1);
        const float x2 = __ldg(tg + 2), y2 = __ldg(tg + 3);
        const float cl = __ldg(tg + 4);
        s_ti[tid][0] = x1; s_ti[tid][1] = y1;
        s_ti[tid][2] = x2; s_ti[tid][3] = y2;
        s_ti[tid][4] = cl;
        const float lx = (x1 + x2) * 0.5f;
        const float ly = (y1 + y2) * 0.5f;
        s_idx[tid] = (int)floorf(ly / 32.0f) * NG + (int)floorf(lx / 32.0f);
    }
    __syncthreads();   // sync 1: s_idx/s_ti visible

    // ---- phase 1: staged row gather (21 consecutive threads per row) ----
    if (tid < 504) {
        const int r0  = tid / ROWLEN;        // 0..23
        const int col = tid - r0 * ROWLEN;   // 0..20
        #pragma unroll
        for (int it = 0; it < 4; it++) {
            const int row = it * 24 + r0;
            if (row < 90) {
                const int t = row / 3;
                const int a = row - t * 3;
                s_p[row * PSTRIDE + col] =
                    __ldg(outp + base + ((size_t)s_idx[t] * 3 + a) * ROWLEN + col);
            }
        }
    }
    __syncthreads();   // sync 2: s_p visible

    // ---- phase 2: per-row loss ----
    const float SQRT5 = 2.2360679774997896f;
    const float INVW  = 1.0f / 416.0f;
    float acc = 0.0f;
    if (tid < NROWS) {
        const int cell = tid / 3;
        const int a    = tid - cell * 3;

        // find owning target via broadcast scan (cells distinct; -1 if none)
        int t = -1;
        #pragma unroll
        for (int k = 0; k < NT; k++)
            if (s_idx[k] == cell) t = k;

        if (t < 0) {
            acc = conf * conf;
        } else {
            const float x1 = s_ti[t][0], y1 = s_ti[t][1];
            const float x2 = s_ti[t][2], y2 = s_ti[t][3];
            const float a2 = (x2 - x1) * (y2 - y1);
            float iou[3];
            #pragma unroll
            for (int aa = 0; aa < 3; aa++) {
                const float* p = s_p + (t * 3 + aa) * PSTRIDE;
                const float px = p[0], py = p[1], pw = p[2], ph = p[3];
                const float bx1 = px - pw * 0.5f, by1 = py - ph * 0.5f;
                const float bx2 = px + pw * 0.5f, by2 = py + ph * 0.5f;
                const float ix1 = fmaxf(bx1, x1), iy1 = fmaxf(by1, y1);
                const float ix2 = fminf(bx2, x2), iy2 = fminf(by2, y2);
                const float inter = fmaxf(ix2 - ix1, 0.0f) * fmaxf(iy2 - iy1, 0.0f);
                const float a1 = (bx2 - bx1) * (by2 - by1);
                iou[aa] = inter / (a1 + a2 - inter + 1e-16f);
            }
            float best = iou[0]; int best_a = 0;
            if (iou[1] > best) { best = iou[1]; best_a = 1; }
            if (iou[2] > best) { best = iou[2]; best_a = 2; }

            if (a == best_a) {
                const float d = (conf - best) * SQRT5;
                acc = d * d;
                const float* p = s_p + (t * 3 + a) * PSTRIDE;
                const float lx = (x1 + x2) * 0.5f;
                const float ly = (y1 + y2) * 0.5f;
                const float tw = x2 - x1, th = y2 - y1;
                const float k  = (2.0f - (tw * INVW) * (th * INVW)) * INVW;
                const float dx = (p[0] - lx) * k;
                const float dy = (p[1] - ly) * k;
                const float dw = (p[2] - tw) * k;
                const float dh = (p[3] - th) * k;
                acc += dx*dx + dy*dy + dw*dw + dh*dh;
                const int c0 = (int)s_ti[t][4];
                #pragma unroll
                for (int c = 0; c < NC; c++) {
                    const float d2 = p[5 + c] - (c == c0 ? 1.0f : 0.0f);
                    acc += d2 * d2;
                }
            } else {
                const float cm = (iou[a] > 0.5f) ? 0.0f : 1.0f;
                const float d  = conf * cm;
                acc = d * d;
            }
        }
    }
    acc *= 0.5f;

    // ---- block reduce ----
    acc = warp_sum(acc);
    const int lane = tid & 31, wid = tid >> 5;
    if (lane == 0) s_warp[wid] = acc;
    __syncthreads();
    if (wid == 0) {
        float x = (lane < 16) ? s_warp[lane] : 0.0f;
        x = warp_sum(x);
        if (lane == 0) {
            // ONE fire-and-forget 64-bit RED carries both count and sum:
            // high 8 bits: +1 arrival; low 56 bits: fixed-point partial (non-negative)
            const double SCALE = 16777216.0;   // 2^24
            const unsigned long long fx =
                (unsigned long long)__double2ll_rn((double)x * SCALE);
            atomicAdd(&g_pack, (1ULL << 56) | fx);

            if (b == 0) {
                // only block 0 waits; single packed word = no ordering hazards
                unsigned long long v;
                do {
                    v = *((volatile unsigned long long*)&g_pack);
                } while ((v >> 56) < (unsigned long long)NB);
                const long long sum = (long long)(v & ((1ULL << 56) - 1ULL));
                loss[0] = (float)((double)sum / SCALE);         // publish
                *((volatile unsigned long long*)&g_pack) = 0ULL; // reset for next replay
            }
        }
    }
}

extern "C" void kernel_launch(void* const* d_in, const int* in_sizes, int n_in,
                              void* d_out, int out_size) {
    const float* outp = (const float*)d_in[0];
    const float* tgt  = (const float*)d_in[1];
    float* loss = (float*)d_out;
    region_loss_kernel<<<NB, 512>>>(outp, tgt, loss);
}

// round 12
// speedup vs baseline: 1.0895x; 1.0895x over previous
#include <cuda_runtime.h>
#include <math.h>

#define NB 128
#define NT 30
#define NG 13
#define NC 16
#define NCELLS 169
#define NROWS 507            // 169*3 anchor rows used per batch
#define ROWLEN 21
#define ROWS_FULL 10647
#define PSTRIDE 22           // padded row stride in smem

__device__ __forceinline__ float warp_sum(float v) {
    #pragma unroll
    for (int o = 16; o > 0; o >>= 1) v += __shfl_down_sync(0xffffffffu, v, o);
    return v;
}

__global__ void __launch_bounds__(512) region_loss_kernel(
    const float* __restrict__ outp,   // (128, 10647, 21)
    const float* __restrict__ tgt,    // (128, 30, 5)
    float* __restrict__ loss)
{
    const int b   = blockIdx.x;
    const int tid = threadIdx.x;
    const size_t base = (size_t)b * ((size_t)ROWS_FULL * ROWLEN);

    __shared__ float s_tgt[NT * 5];
    __shared__ int   s_cell2t[NCELLS];
    __shared__ float s_p[90 * PSTRIDE];      // staged target rows
    __shared__ float s_locx[NT], s_locy[NT], s_tw[NT], s_th[NT], s_k[NT];
    __shared__ int   s_cls[NT];
    __shared__ float s_iou[NT][3];
    __shared__ float s_extra[NT][3];         // coord+class loss per (t,a)
    __shared__ float s_warp[16];

    // ---- phase 0: independent global loads issued immediately ----
    float conf = 0.0f;
    if (tid < NROWS)  conf = __ldg(outp + base + (size_t)tid * ROWLEN + 4);
    if (tid < NT * 5) s_tgt[tid] = __ldg(tgt + (size_t)b * (NT * 5) + tid);
    if (tid < NCELLS) s_cell2t[tid] = -1;
    __syncthreads();   // s_tgt + cell2t init visible

    // ---- phase 1: staged row gather (21 consecutive threads per row) ----
    {
        const int r0  = tid / ROWLEN;        // 0..24 (tid<504)
        const int col = tid - r0 * ROWLEN;   // 0..20
        #pragma unroll
        for (int it = 0; it < 4; it++) {
            const int row = it * 24 + r0;
            if (tid < 504 && row < 90) {
                const int t = row / 3;
                const int a = row - t * 3;
                const float lx = (s_tgt[t*5+0] + s_tgt[t*5+2]) * 0.5f;
                const float ly = (s_tgt[t*5+1] + s_tgt[t*5+3]) * 0.5f;
                const int idx = (int)floorf(ly / 32.0f) * NG + (int)floorf(lx / 32.0f);
                s_p[row * PSTRIDE + col] =
                    __ldg(outp + base + ((size_t)idx * 3 + a) * ROWLEN + col);
            }
        }
    }
    // ---- concurrent: per-target scalars (30 threads, reads only s_tgt) ----
    if (tid < NT) {
        const float x1 = s_tgt[tid*5+0], y1 = s_tgt[tid*5+1];
        const float x2 = s_tgt[tid*5+2], y2 = s_tgt[tid*5+3];
        const float lx = (x1 + x2) * 0.5f;
        const float ly = (y1 + y2) * 0.5f;
        const int idx = (int)floorf(ly / 32.0f) * NG + (int)floorf(lx / 32.0f);
        const float tw = x2 - x1, th = y2 - y1;
        const float INVW = 1.0f / 416.0f;
        s_locx[tid] = lx; s_locy[tid] = ly;
        s_tw[tid] = tw;  s_th[tid] = th;
        s_k[tid]  = (2.0f - (tw * INVW) * (th * INVW)) * INVW;
        s_cls[tid] = (int)s_tgt[tid*5+4];
        s_cell2t[idx] = tid;
    }
    __syncthreads();   // s_p + scalar tables visible

    // ---- phase 2: per (t,a) IoU + coord + class loss (90 threads, smem only) ----
    if (tid < NT * 3) {
        const int t = tid / 3;
        const int a = tid - t * 3;
        const float* p = s_p + tid * PSTRIDE;
        const float px = p[0], py = p[1], pw = p[2], ph = p[3];

        const float bx1 = px - pw * 0.5f, by1 = py - ph * 0.5f;
        const float bx2 = px + pw * 0.5f, by2 = py + ph * 0.5f;
        const float x1 = s_tgt[t*5+0], y1 = s_tgt[t*5+1];
        const float x2 = s_tgt[t*5+2], y2 = s_tgt[t*5+3];
        const float ix1 = fmaxf(bx1, x1), iy1 = fmaxf(by1, y1);
        const float ix2 = fminf(bx2, x2), iy2 = fminf(by2, y2);
        const float inter = fmaxf(ix2 - ix1, 0.0f) * fmaxf(iy2 - iy1, 0.0f);
        const float a1 = (bx2 - bx1) * (by2 - by1);
        const float a2 = (x2 - x1) * (y2 - y1);
        s_iou[t][a] = inter / (a1 + a2 - inter + 1e-16f);

        // coord loss
        const float k  = s_k[t];
        const float dx = (px - s_locx[t]) * k;
        const float dy = (py - s_locy[t]) * k;
        const float dw = (pw - s_tw[t])   * k;
        const float dh = (ph - s_th[t])   * k;
        float ex = dx*dx + dy*dy + dw*dw + dh*dh;

        // class loss
        const int c0 = s_cls[t];
        #pragma unroll
        for (int c = 0; c < NC; c++) {
            const float d = p[5 + c] - (c == c0 ? 1.0f : 0.0f);
            ex += d * d;
        }
        s_extra[t][a] = ex;
    }
    __syncthreads();   // iou/extra tables visible

    // ---- phase 3: per-row loss (argmax recomputed locally; first-max) ----
    const float SQRT5 = 2.2360679774997896f;
    float acc = 0.0f;
    if (tid < NROWS) {
        const int cell = tid / 3;
        const int a    = tid - cell * 3;
        const int t    = s_cell2t[cell];
        if (t < 0) {
            acc = conf * conf;
        } else {
            const float i0 = s_iou[t][0], i1 = s_iou[t][1], i2 = s_iou[t][2];
            float best = i0; int best_a = 0;
            if (i1 > best) { best = i1; best_a = 1; }
            if (i2 > best) { best = i2; best_a = 2; }
            if (a == best_a) {
                const float d = (conf - best) * SQRT5;
                acc = d * d + s_extra[t][a];
            } else {
                const float ia = (a == 0) ? i0 : (a == 1) ? i1 : i2;
                const float cm = (ia > 0.5f) ? 0.0f : 1.0f;
                const float d  = conf * cm;
                acc = d * d;
            }
        }
    }
    acc *= 0.5f;

    // ---- block reduce, then single fire-and-forget atomic (RED) ----
    acc = warp_sum(acc);
    const int lane = tid & 31, wid = tid >> 5;
    if (lane == 0) s_warp[wid] = acc;
    __syncthreads();
    if (wid == 0) {
        float x = (lane < 16) ? s_warp[lane] : 0.0f;
        x = warp_sum(x);
        if (lane == 0) atomicAdd(loss, x);   // result unused -> RED, no wait
    }
}

extern "C" void kernel_launch(void* const* d_in, const int* in_sizes, int n_in,
                              void* d_out, int out_size) {
    const float* outp = (const float*)d_in[0];
    const float* tgt  = (const float*)d_in[1];
    float* loss = (float*)d_out;
    cudaMemsetAsync(loss, 0, sizeof(float));      // cheap graph memset node
    region_loss_kernel<<<NB, 512>>>(outp, tgt, loss);
}